// round 9
// baseline (speedup 1.0000x reference)
#include <cuda_runtime.h>
#include <cuda_bf16.h>

#define GN 512
#define IMG_H 512
#define IMG_W 512
#define TILES_X 32
#define TILES_Y 32

// tanh(x) = 1 - 2/(exp(2x)+1)
__device__ __forceinline__ float fast_tanh(float x) {
    return 1.0f - __fdividef(2.0f, __expf(2.0f * x) + 1.0f);
}

// Grid: (16, 32). Each CTA = 512 threads = two horizontally adjacent 16x16
// tiles (a 32x16 pixel strip). Each thread culls exactly ONE gaussian and
// renders exactly ONE pixel.
__global__ __launch_bounds__(512) void render_dual_kernel(
    const float* __restrict__ xyz,
    const float* __restrict__ chol,
    const float* __restrict__ feat,
    const float* __restrict__ opac,
    float* __restrict__ out)
{
    const int gx  = blockIdx.x;          // tile-pair column in [0,16)
    const int ty  = blockIdx.y;          // tile row in [0,32)
    const int tx0 = gx * 2;              // left tile column
    const int lx  = threadIdx.x;         // [0,32)
    const int ly  = threadIdx.y;         // [0,16)
    const int tid = ly * 32 + lx;        // [0,512)
    const int lane = tid & 31;

    __shared__ float4 s_p0[GN];          // cx, cy, 0.5*ca, cb
    __shared__ float4 s_p1[GN];          // 0.5*cc, f0*o, f1*o, f2*o
    __shared__ int    s_m[GN];           // 2-bit tile-column mask
    __shared__ int s_count;
    if (tid == 0) s_count = 0;
    __syncthreads();

    // Phase A: one gaussian per thread, cheap cull, heavy math only for
    // survivors (~4 threads per CTA).
    {
        const int i = tid;

        float2 xy = ((const float2*)xyz)[i];
        float l0 = chol[3*i + 0] + 0.5f;
        float l1 = chol[3*i + 1];
        float l2 = chol[3*i + 2] + 0.5f;

        float cx = 256.0f * (fast_tanh(xy.x) + 1.0f);
        float cy = 256.0f * (fast_tanh(xy.y) + 1.0f);

        float cxx = l0 * l0;
        float cxy = l0 * l1;
        float cyy = l1 * l1 + l2 * l2;
        float det = cxx * cyy - cxy * cxy;

        float b  = 0.5f * (cxx + cyy);
        float v1 = fmaxf(b * b - det, 0.1f);
        v1 = b + v1 * rsqrtf(v1);                       // b + sqrt(.)
        float radius = ceilf(3.0f * v1 * rsqrtf(v1));   // ceil(3*sqrt(v1))

        // Unclamped bounds equivalent to clamped for tx,ty in [0,32)
        int tminx = (int)((cx - radius) * 0.0625f);
        int tmaxx = (int)((cx + radius) * 0.0625f) + 1;
        int tminy = (int)((cy - radius) * 0.0625f);
        int tmaxy = (int)((cy + radius) * 0.0625f) + 1;

        bool iny = (ty >= tminy) && (ty < tmaxy);
        bool in0 = iny && (tx0     >= tminx) && (tx0     < tmaxx);
        bool in1 = iny && (tx0 + 1 >= tminx) && (tx0 + 1 < tmaxx);
        bool pred = in0 || in1;

        unsigned m = __ballot_sync(0xffffffffu, pred);
        if (m) {
            int base = 0;
            if (lane == 0) base = atomicAdd(&s_count, __popc(m));
            base = __shfl_sync(0xffffffffu, base, 0);
            if (pred) {
                float inv_det = __fdividef(1.0f, det);
                float o = opac[i];
                int p = base + __popc(m & ((1u << lane) - 1u));
                s_p0[p] = make_float4(cx, cy, 0.5f * cyy * inv_det, -cxy * inv_det);
                s_p1[p] = make_float4(0.5f * cxx * inv_det,
                                      feat[3*i + 0] * o,
                                      feat[3*i + 1] * o,
                                      feat[3*i + 2] * o);
                s_m[p] = (in0 ? 1 : 0) | (in1 ? 2 : 0);
            }
        }
    }
    __syncthreads();
    const int cnt = s_count;

    // Phase B: one pixel per thread.
    const float px = (float)(gx * 32 + lx);
    const float py = (float)(ty * 16 + ly);
    const int   qx = lx >> 4;            // which tile of the pair

    float acc0 = 0.0f, acc1 = 0.0f, acc2 = 0.0f;
    for (int k = 0; k < cnt; k++) {
        float4 p0 = s_p0[k];             // broadcast LDS
        float4 p1 = s_p1[k];
        float inb = (float)((s_m[k] >> qx) & 1);
        float dx = p0.x - px;
        float dy = p0.y - py;
        float sigma = p0.z * dx * dx + p1.x * dy * dy + p0.w * dx * dy;
        float w = inb * __expf(-sigma);
        acc0 += w * p1.y;
        acc1 += w * p1.z;
        acc2 += w * p1.w;
    }

    acc0 = fminf(fmaxf(acc0, 0.0f), 1.0f);
    acc1 = fminf(fmaxf(acc1, 0.0f), 1.0f);
    acc2 = fminf(fmaxf(acc2, 0.0f), 1.0f);

    const int pix = (ty * 16 + ly) * IMG_W + (gx * 32 + lx);
    out[0 * IMG_H * IMG_W + pix] = acc0;
    out[1 * IMG_H * IMG_W + pix] = acc1;
    out[2 * IMG_H * IMG_W + pix] = acc2;
}

extern "C" void kernel_launch(void* const* d_in, const int* in_sizes, int n_in,
                              void* d_out, int out_size)
{
    const float* xyz  = (const float*)d_in[0];
    const float* chol = (const float*)d_in[1];
    const float* feat = (const float*)d_in[2];
    const float* opac = (const float*)d_in[3];
    float* out = (float*)d_out;

    dim3 grid(16, 32);
    dim3 block(32, 16);
    render_dual_kernel<<<grid, block>>>(xyz, chol, feat, opac, out);
}